// round 3
// baseline (speedup 1.0000x reference)
#include <cuda_runtime.h>
#include <stdint.h>

// Problem constants (fixed shapes from reference):
//   updates: (32, 64, 64, 128) fp32  -> 16,777,216 elems
//   mask:    same shape, int32 in [0, 2,097,152)
//   output:  (32, 128, 128, 128) fp32 -> 67,108,864 elems (256 MB)
#define N_IN        16777216     // total update elements
#define PER_B_IN    524288       // 64*64*128 per-batch input elements
#define FLAT_OUT    2097152      // 128*128*128 per-batch output slots
#define N_OUT       67108864     // 32 * FLAT_OUT
#define LOG2_PERB_V 17           // PER_B_IN/4 = 131072 = 2^17 (vec4 elements per batch)

// ---------------------------------------------------------------------------
// Kernel 1: zero the whole output (it is 0xAA-poisoned by the harness).
// float4 stores -> STG.128, pure DRAM-write bound (~256 MB).
// ---------------------------------------------------------------------------
__global__ void __launch_bounds__(256) zero_out_kernel(float4* __restrict__ out) {
    const int n4 = N_OUT / 4;  // 16,777,216 float4s
    int i = blockIdx.x * blockDim.x + threadIdx.x;
    const float4 z = make_float4(0.f, 0.f, 0.f, 0.f);
    // grid exactly covers n4; no stride loop needed, but guard anyway
    if (i < n4) out[i] = z;
}

// ---------------------------------------------------------------------------
// Kernel 2: scatter-add. Each thread handles 4 consecutive elements
// (one float4 of updates + one int4 of mask). All 4 belong to the same
// batch because PER_B_IN is divisible by 4. atomicAdd with unused return
// -> RED.E.ADD.F32 (no round trip). Blocks are naturally ordered by batch,
// which keeps each 8 MB per-batch output window hot in L2 while its
// scatters are in flight.
// ---------------------------------------------------------------------------
__global__ void __launch_bounds__(256) scatter_add_kernel(
    const float4* __restrict__ upd,
    const int4*   __restrict__ mask,
    float*        __restrict__ out)
{
    const int n4 = N_IN / 4;  // 4,194,304 vec elements
    int i = blockIdx.x * blockDim.x + threadIdx.x;
    if (i >= n4) return;

    float4 u = upd[i];
    int4   m = mask[i];

    int b = i >> LOG2_PERB_V;                 // batch index
    float* obase = out + (size_t)b * FLAT_OUT;

    atomicAdd(obase + m.x, u.x);
    atomicAdd(obase + m.y, u.y);
    atomicAdd(obase + m.z, u.z);
    atomicAdd(obase + m.w, u.w);
}

extern "C" void kernel_launch(void* const* d_in, const int* in_sizes, int n_in,
                              void* d_out, int out_size)
{
    const float4* upd  = (const float4*)d_in[0];   // updates fp32
    const int4*   mask = (const int4*)  d_in[1];   // mask int32
    float*        out  = (float*)d_out;

    // Zero pass: 16,777,216 float4s / 256 threads = 65,536 blocks
    zero_out_kernel<<<N_OUT / 4 / 256, 256>>>((float4*)out);

    // Scatter pass: 4,194,304 vec elements / 256 threads = 16,384 blocks
    scatter_add_kernel<<<N_IN / 4 / 256, 256>>>(upd, mask, out);
}